// round 4
// baseline (speedup 1.0000x reference)
#include <cuda_runtime.h>

#define OBS_LEN 20
#define PRED_LEN 30
#define MAXN 131072
#define BT 64            // block size for LSTM kernels

typedef unsigned long long u64;

// ---------------- f32x2 / MUFU helpers ----------------
__device__ __forceinline__ u64 fma2(u64 a, u64 b, u64 c) {
    u64 d;
    asm("fma.rn.f32x2 %0, %1, %2, %3;" : "=l"(d) : "l"(a), "l"(b), "l"(c));
    return d;
}
__device__ __forceinline__ u64 pack2(float lo, float hi) {
    u64 d;
    asm("mov.b64 %0, {%1, %2};" : "=l"(d) : "f"(lo), "f"(hi));
    return d;
}
__device__ __forceinline__ float2 unpack2(u64 v) {
    float2 r;
    asm("mov.b64 {%0, %1}, %2;" : "=f"(r.x), "=f"(r.y) : "l"(v));
    return r;
}
__device__ __forceinline__ float hsum2(u64 v) {
    float2 s = unpack2(v);
    return s.x + s.y;
}
__device__ __forceinline__ float tanha(float x) {
    float r;
    asm("tanh.approx.f32 %0, %1;" : "=f"(r) : "f"(x));
    return r;
}
__device__ __forceinline__ float sigt(float x) {
    return fmaf(0.5f, tanha(0.5f * x), 0.5f);
}

// ---------------- scratch ----------------
__device__ float g_h[32 * MAXN];   // h_enc (post-LN), transposed [k][N]
__device__ float g_d[32 * MAXN];   // decoder init h,  transposed [k][N]

// ---------------- dual-agent LSTM step ----------------
// hpA/hpB: h packed pairs (16 u64 each). xA/xB: packed inputs.
// cA/cB: shared c state, stride BT (+tid applied by caller).
// wxb[r] = { pack(wx0, wx1), pack(bias, 0) } -> bias folded into acc init.
__device__ __forceinline__ void lstm_step_dual(
    u64 *hpA, u64 *hpB, u64 xA, u64 xB,
    const float *__restrict__ whh, const ulonglong2 *__restrict__ wxb,
    float *cA, float *cB)
{
    float hnA[32], hnB[32];
#pragma unroll 2
    for (int j = 0; j < 32; j++) {
        float gvA[4], gvB[4];
#pragma unroll
        for (int g = 0; g < 4; g++) {
            const int r = g * 32 + j;
            const ulonglong2 *wr = (const ulonglong2 *)(whh + r * 32);
            ulonglong2 wx = wxb[r];
            u64 aA = fma2(wx.x, xA, wx.y);   // bias in acc (lo lane)
            u64 aB = fma2(wx.x, xB, wx.y);
#pragma unroll
            for (int kk = 0; kk < 8; kk++) {
                ulonglong2 w = wr[kk];
                aA = fma2(w.x, hpA[2 * kk], aA);
                aB = fma2(w.x, hpB[2 * kk], aB);
                aA = fma2(w.y, hpA[2 * kk + 1], aA);
                aB = fma2(w.y, hpB[2 * kk + 1], aB);
            }
            gvA[g] = hsum2(aA);
            gvB[g] = hsum2(aB);
        }
        {
            float cj = fmaf(sigt(gvA[1]), cA[j * BT], sigt(gvA[0]) * tanha(gvA[2]));
            cA[j * BT] = cj;
            hnA[j] = sigt(gvA[3]) * tanha(cj);
        }
        {
            float cj = fmaf(sigt(gvB[1]), cB[j * BT], sigt(gvB[0]) * tanha(gvB[2]));
            cB[j * BT] = cj;
            hnB[j] = sigt(gvB[3]) * tanha(cj);
        }
    }
#pragma unroll
    for (int k = 0; k < 16; k++) {
        hpA[k] = pack2(hnA[2 * k], hnA[2 * k + 1]);
        hpB[k] = pack2(hnB[2 * k], hnB[2 * k + 1]);
    }
}

__device__ __forceinline__ float dot32p(const float *__restrict__ row, const u64 *hp)
{
    const ulonglong2 *wr = (const ulonglong2 *)row;
    u64 acc = 0ULL;
#pragma unroll
    for (int kk = 0; kk < 8; kk++) {
        ulonglong2 w = wr[kk];
        acc = fma2(w.x, hp[2 * kk], acc);
        acc = fma2(w.y, hp[2 * kk + 1], acc);
    }
    return hsum2(acc);
}
__device__ __forceinline__ float dot64p(const float *__restrict__ row, const u64 *hp)
{
    const ulonglong2 *wr = (const ulonglong2 *)row;
    u64 acc = 0ULL;
#pragma unroll
    for (int kk = 0; kk < 16; kk++) {
        ulonglong2 w = wr[kk];
        acc = fma2(w.x, hp[2 * kk], acc);
        acc = fma2(w.y, hp[2 * kk + 1], acc);
    }
    return hsum2(acc);
}

// smem (floats): [whh 4096][wxb 512][extra E][cA 32*BT][cB 32*BT]
#define ENC_EXTRA 64    // lng 32 + lnb 32
#define DEC_EXTRA 66    // outw 64 + outb 2
#define SM_WXB 4096
#define SM_EXTRA (SM_WXB + 512)
#define ENC_SMEM ((SM_EXTRA + ENC_EXTRA + 2 * 32 * BT) * 4)
#define DEC_SMEM ((SM_EXTRA + DEC_EXTRA + 2 + 2 * 32 * BT) * 4)

__device__ __forceinline__ void fold_wx(
    ulonglong2 *wxb, int g,
    const float *__restrict__ wih, const float *__restrict__ bih,
    const float *__restrict__ bhh, const float *__restrict__ embw,
    const float *__restrict__ embb)
{
    float w0 = 0.f, w1 = 0.f, b = bih[g] + bhh[g];
#pragma unroll
    for (int e = 0; e < 16; e++) {
        float wie = wih[g * 16 + e];
        w0 = fmaf(wie, embw[e * 2 + 0], w0);
        w1 = fmaf(wie, embw[e * 2 + 1], w1);
        b = fmaf(wie, embb[e], b);
    }
    wxb[g].x = pack2(w0, w1);
    wxb[g].y = pack2(b, 0.f);
}

// ================= K1: encoder LSTM + LayerNorm (2 agents/thread) =================
__global__ void __launch_bounds__(BT, 6)
k_enc(const float *__restrict__ rel,
      const float *__restrict__ wih, const float *__restrict__ whh_g,
      const float *__restrict__ bih, const float *__restrict__ bhh,
      const float *__restrict__ embw, const float *__restrict__ embb,
      const float *__restrict__ lng_g, const float *__restrict__ lnb_g, int n)
{
    extern __shared__ float sm[];
    float *whh = sm;
    ulonglong2 *wxb = (ulonglong2 *)(sm + SM_WXB);
    float *lng = sm + SM_EXTRA;
    float *lnb = lng + 32;
    float *cAs = sm + SM_EXTRA + ENC_EXTRA;
    float *cBs = cAs + 32 * BT;

    const int tid = threadIdx.x;
    for (int i = tid; i < 4096; i += BT) whh[i] = whh_g[i];
    for (int g = tid; g < 128; g += BT)
        fold_wx(wxb, g, wih, bih, bhh, embw, embb);
    if (tid < 32) { lng[tid] = lng_g[tid]; lnb[tid] = lnb_g[tid]; }
    __syncthreads();

    const int half = n >> 1;
    const int aA = blockIdx.x * BT + tid;
    if (aA >= half) return;
    const int aB = aA + half;
    float *cA = cAs + tid, *cB = cBs + tid;

    u64 hpA[16], hpB[16];
#pragma unroll
    for (int k = 0; k < 16; k++) { hpA[k] = 0ULL; hpB[k] = 0ULL; }
#pragma unroll
    for (int j = 0; j < 32; j++) { cA[j * BT] = 0.f; cB[j * BT] = 0.f; }

    const float2 *rel2 = (const float2 *)rel;
#pragma unroll 1
    for (int t = 0; t < OBS_LEN; t++) {
        float2 xa = __ldg(&rel2[(size_t)t * n + aA]);
        float2 xb = __ldg(&rel2[(size_t)t * n + aB]);
        lstm_step_dual(hpA, hpB, pack2(xa.x, xa.y), pack2(xb.x, xb.y),
                       whh, wxb, cA, cB);
    }

#pragma unroll
    for (int sel = 0; sel < 2; sel++) {
        const u64 *hp = sel ? hpB : hpA;
        const int ag = sel ? aB : aA;
        float hv[32];
#pragma unroll
        for (int k = 0; k < 16; k++) {
            float2 p = unpack2(hp[k]);
            hv[2 * k] = p.x;
            hv[2 * k + 1] = p.y;
        }
        float m = 0.f;
#pragma unroll
        for (int j = 0; j < 32; j++) m += hv[j];
        m *= (1.f / 32.f);
        float v = 0.f;
#pragma unroll
        for (int j = 0; j < 32; j++) { float d = hv[j] - m; v = fmaf(d, d, v); }
        float inv = rsqrtf(v * (1.f / 32.f) + 1e-5f);
#pragma unroll
        for (int j = 0; j < 32; j++)
            g_h[(size_t)j * n + ag] = fmaf((hv[j] - m) * inv, lng[j], lnb[j]);
    }
}

// ================= K2: attention + context LN + MLP (128-thr CTAs) =================
#define ATH 128
struct AttnSmem {
    float wq[1024], wk[1024], wv[1024], wo[1024];
    float mlp1[4096], mlp2[1536];
    float lncg[64], lncb[64], m1b[64], m2b[24], noi[8];
    float kbuf[4][32][40];
    float vbuf[4][32][40];
};

__global__ void __launch_bounds__(ATH)
k_attn(const float *__restrict__ wq_g, const float *__restrict__ wk_g,
       const float *__restrict__ wv_g, const float *__restrict__ wo_g,
       const float *__restrict__ lncg, const float *__restrict__ lncb,
       const float *__restrict__ m1w, const float *__restrict__ m1b,
       const float *__restrict__ m2w, const float *__restrict__ m2b,
       const float *__restrict__ noi, int n)
{
    extern __shared__ char smem_raw[];
    AttnSmem *s = (AttnSmem *)smem_raw;
    const int tid = threadIdx.x;
#define CP(d, src, c) for (int _i = tid; _i < (c); _i += ATH) (d)[_i] = (src)[_i];
    CP(s->wq, wq_g, 1024) CP(s->wk, wk_g, 1024) CP(s->wv, wv_g, 1024) CP(s->wo, wo_g, 1024)
    CP(s->mlp1, m1w, 4096) CP(s->mlp2, m2w, 1536)
    CP(s->lncg, lncg, 64) CP(s->lncb, lncb, 64)
    CP(s->m1b, m1b, 64) CP(s->m2b, m2b, 24) CP(s->noi, noi, 8)
#undef CP
    __syncthreads();

    const int agent = blockIdx.x * ATH + tid;
    if (agent >= n) return;
    const int warp = tid >> 5, lane = tid & 31;

    float hv[32];
#pragma unroll
    for (int k = 0; k < 32; k++) hv[k] = __ldg(&g_h[(size_t)k * n + agent]);
    u64 hp[16];
#pragma unroll
    for (int k = 0; k < 16; k++) hp[k] = pack2(hv[2 * k], hv[2 * k + 1]);

    float q[32];
#pragma unroll
    for (int d = 0; d < 32; d++) {
        q[d] = dot32p(s->wq + d * 32, hp);
        s->kbuf[warp][lane][d] = dot32p(s->wk + d * 32, hp);
        s->vbuf[warp][lane][d] = dot32p(s->wv + d * 32, hp);
    }
    __syncwarp();

    float att[32];
#pragma unroll
    for (int hh = 0; hh < 4; hh++) {
        u64 qp[4];
#pragma unroll
        for (int i = 0; i < 4; i++) qp[i] = pack2(q[hh * 8 + 2 * i], q[hh * 8 + 2 * i + 1]);
        float sc[32], mx = -1e30f;
#pragma unroll
        for (int j = 0; j < 32; j++) {
            const ulonglong2 *kr = (const ulonglong2 *)&s->kbuf[warp][j][hh * 8];
            ulonglong2 k01 = kr[0], k23 = kr[1];
            u64 acc = fma2(k01.x, qp[0], 0ULL);
            acc = fma2(k01.y, qp[1], acc);
            acc = fma2(k23.x, qp[2], acc);
            acc = fma2(k23.y, qp[3], acc);
            float d0 = hsum2(acc) * 0.35355339059327373f;
            sc[j] = d0;
            mx = fmaxf(mx, d0);
        }
        float sum = 0.f;
#pragma unroll
        for (int j = 0; j < 32; j++) {
            float e = __expf(sc[j] - mx);
            sc[j] = e;
            sum += e;
        }
        float inv = __fdividef(1.f, sum);
        u64 a0 = 0, a1 = 0, a2 = 0, a3 = 0;
#pragma unroll
        for (int j = 0; j < 32; j++) {
            const ulonglong2 *vr = (const ulonglong2 *)&s->vbuf[warp][j][hh * 8];
            ulonglong2 v01 = vr[0], v23 = vr[1];
            u64 pd = pack2(sc[j], sc[j]);
            a0 = fma2(v01.x, pd, a0);
            a1 = fma2(v01.y, pd, a1);
            a2 = fma2(v23.x, pd, a2);
            a3 = fma2(v23.y, pd, a3);
        }
        float2 r0 = unpack2(a0), r1 = unpack2(a1), r2 = unpack2(a2), r3 = unpack2(a3);
        att[hh * 8 + 0] = r0.x * inv; att[hh * 8 + 1] = r0.y * inv;
        att[hh * 8 + 2] = r1.x * inv; att[hh * 8 + 3] = r1.y * inv;
        att[hh * 8 + 4] = r2.x * inv; att[hh * 8 + 5] = r2.y * inv;
        att[hh * 8 + 6] = r3.x * inv; att[hh * 8 + 7] = r3.y * inv;
    }

    u64 ap[16];
#pragma unroll
    for (int k = 0; k < 16; k++) ap[k] = pack2(att[2 * k], att[2 * k + 1]);
    float ctx[64];
#pragma unroll
    for (int j = 0; j < 32; j++) ctx[j] = hv[j];
#pragma unroll
    for (int d = 0; d < 32; d++) ctx[32 + d] = dot32p(s->wo + d * 32, ap);

    {
        float m = 0.f;
#pragma unroll
        for (int j = 0; j < 64; j++) m += ctx[j];
        m *= (1.f / 64.f);
        float v = 0.f;
#pragma unroll
        for (int j = 0; j < 64; j++) { float d = ctx[j] - m; v = fmaf(d, d, v); }
        float inv = rsqrtf(v * (1.f / 64.f) + 1e-5f);
#pragma unroll
        for (int j = 0; j < 64; j++)
            ctx[j] = fmaf((ctx[j] - m) * inv, s->lncg[j], s->lncb[j]);
    }

    u64 cp[32];
#pragma unroll
    for (int k = 0; k < 32; k++) cp[k] = pack2(ctx[2 * k], ctx[2 * k + 1]);
    float y1[64];
#pragma unroll
    for (int m = 0; m < 64; m++) {
        float a = dot64p(s->mlp1 + m * 64, cp) + s->m1b[m];
        y1[m] = (a > 0.f) ? a : 0.01f * a;
    }
    u64 yp[32];
#pragma unroll
    for (int k = 0; k < 32; k++) yp[k] = pack2(y1[2 * k], y1[2 * k + 1]);
#pragma unroll
    for (int m = 0; m < 24; m++) {
        float a = dot64p(s->mlp2 + m * 64, yp) + s->m2b[m];
        a = (a > 0.f) ? a : 0.01f * a;
        g_d[(size_t)m * n + agent] = a;
    }
#pragma unroll
    for (int m = 0; m < 8; m++) g_d[(size_t)(24 + m) * n + agent] = s->noi[m];
}

// ================= K3: decoder LSTM rollout (2 agents/thread) =================
__global__ void __launch_bounds__(BT, 6)
k_dec(const float *__restrict__ rel,
      const float *__restrict__ wih, const float *__restrict__ whh_g,
      const float *__restrict__ bih, const float *__restrict__ bhh,
      const float *__restrict__ embw, const float *__restrict__ embb,
      const float *__restrict__ outw_g, const float *__restrict__ outb_g,
      float *__restrict__ out, int n)
{
    extern __shared__ float sm[];
    float *whh = sm;
    ulonglong2 *wxb = (ulonglong2 *)(sm + SM_WXB);
    float *outw = sm + SM_EXTRA;
    float *outb = outw + 64;
    float *cAs = sm + SM_EXTRA + DEC_EXTRA + 2;   // 16B align
    float *cBs = cAs + 32 * BT;

    const int tid = threadIdx.x;
    for (int i = tid; i < 4096; i += BT) whh[i] = whh_g[i];
    for (int g = tid; g < 128; g += BT)
        fold_wx(wxb, g, wih, bih, bhh, embw, embb);
    if (tid < 64) outw[tid] = outw_g[tid];
    if (tid < 2) outb[tid] = outb_g[tid];
    __syncthreads();

    const int half = n >> 1;
    const int aA = blockIdx.x * BT + tid;
    if (aA >= half) return;
    const int aB = aA + half;
    float *cA = cAs + tid, *cB = cBs + tid;

    u64 hpA[16], hpB[16];
#pragma unroll
    for (int k = 0; k < 16; k++) {
        hpA[k] = pack2(g_d[(size_t)(2 * k) * n + aA], g_d[(size_t)(2 * k + 1) * n + aA]);
        hpB[k] = pack2(g_d[(size_t)(2 * k) * n + aB], g_d[(size_t)(2 * k + 1) * n + aB]);
    }
#pragma unroll
    for (int j = 0; j < 32; j++) { cA[j * BT] = 0.f; cB[j * BT] = 0.f; }

    const float2 *rel2 = (const float2 *)rel;
    float2 *out2 = (float2 *)out;
    float2 xa = __ldg(&rel2[(size_t)(OBS_LEN - 1) * n + aA]);
    float2 xb = __ldg(&rel2[(size_t)(OBS_LEN - 1) * n + aB]);

#pragma unroll 1
    for (int t = 0; t < PRED_LEN; t++) {
        lstm_step_dual(hpA, hpB, pack2(xa.x, xa.y), pack2(xb.x, xb.y),
                       whh, wxb, cA, cB);
        float oxA = dot32p(outw, hpA) + outb[0];
        float oyA = dot32p(outw + 32, hpA) + outb[1];
        float oxB = dot32p(outw, hpB) + outb[0];
        float oyB = dot32p(outw + 32, hpB) + outb[1];
        out2[(size_t)t * n + aA] = make_float2(oxA, oyA);
        out2[(size_t)t * n + aB] = make_float2(oxB, oyB);
        xa = make_float2(oxA, oyA);
        xb = make_float2(oxB, oyB);
    }
}

// ================= launch =================
extern "C" void kernel_launch(void *const *d_in, const int *in_sizes, int n_in,
                              void *d_out, int out_size)
{
    const float *rel = (const float *)d_in[1];
    const float *noise = (const float *)d_in[3];
    const float *enc_emb_w = (const float *)d_in[4];
    const float *enc_emb_b = (const float *)d_in[5];
    const float *enc_wih = (const float *)d_in[6];
    const float *enc_whh = (const float *)d_in[7];
    const float *enc_bih = (const float *)d_in[8];
    const float *enc_bhh = (const float *)d_in[9];
    const float *lne_g = (const float *)d_in[10];
    const float *lne_b = (const float *)d_in[11];
    const float *wq = (const float *)d_in[12];
    const float *wk = (const float *)d_in[13];
    const float *wv = (const float *)d_in[14];
    const float *wo = (const float *)d_in[15];
    const float *lnc_g = (const float *)d_in[16];
    const float *lnc_b = (const float *)d_in[17];
    const float *mlp1_w = (const float *)d_in[18];
    const float *mlp1_b = (const float *)d_in[19];
    const float *mlp2_w = (const float *)d_in[20];
    const float *mlp2_b = (const float *)d_in[21];
    const float *dec_emb_w = (const float *)d_in[22];
    const float *dec_emb_b = (const float *)d_in[23];
    const float *dec_wih = (const float *)d_in[24];
    const float *dec_whh = (const float *)d_in[25];
    const float *dec_bih = (const float *)d_in[26];
    const float *dec_bhh = (const float *)d_in[27];
    const float *dec_out_w = (const float *)d_in[28];
    const float *dec_out_b = (const float *)d_in[29];

    int n = in_sizes[1] / (OBS_LEN * 2);

    static bool attr_set = false;
    if (!attr_set) {
        cudaFuncSetAttribute(k_attn, cudaFuncAttributeMaxDynamicSharedMemorySize,
                             (int)sizeof(AttnSmem));
        attr_set = true;
    }

    int half = n >> 1;
    int gridp = (half + BT - 1) / BT;

    k_enc<<<gridp, BT, ENC_SMEM>>>(rel, enc_wih, enc_whh, enc_bih, enc_bhh,
                                   enc_emb_w, enc_emb_b, lne_g, lne_b, n);
    k_attn<<<(n + ATH - 1) / ATH, ATH, sizeof(AttnSmem)>>>(
        wq, wk, wv, wo, lnc_g, lnc_b,
        mlp1_w, mlp1_b, mlp2_w, mlp2_b, noise, n);
    k_dec<<<gridp, BT, DEC_SMEM>>>(rel, dec_wih, dec_whh, dec_bih, dec_bhh,
                                   dec_emb_w, dec_emb_b, dec_out_w, dec_out_b,
                                   (float *)d_out, n);
}

// round 5
// speedup vs baseline: 1.0912x; 1.0912x over previous
#include <cuda_runtime.h>

#define OBS_LEN 20
#define PRED_LEN 30
#define MAXN 131072
#define LBT 64           // LSTM kernels: 64 threads = 2 warps/CTA

typedef unsigned long long u64;

// ---------------- f32x2 / MUFU helpers ----------------
__device__ __forceinline__ u64 fma2(u64 a, u64 b, u64 c) {
    u64 d;
    asm("fma.rn.f32x2 %0, %1, %2, %3;" : "=l"(d) : "l"(a), "l"(b), "l"(c));
    return d;
}
__device__ __forceinline__ u64 pack2(float lo, float hi) {
    u64 d;
    asm("mov.b64 %0, {%1, %2};" : "=l"(d) : "f"(lo), "f"(hi));
    return d;
}
__device__ __forceinline__ float2 unpack2(u64 v) {
    float2 r;
    asm("mov.b64 {%0, %1}, %2;" : "=f"(r.x), "=f"(r.y) : "l"(v));
    return r;
}
__device__ __forceinline__ float hsum2(u64 v) {
    float2 s = unpack2(v);
    return s.x + s.y;
}
__device__ __forceinline__ float tanha(float x) {
    float r;
    asm("tanh.approx.f32 %0, %1;" : "=f"(r) : "f"(x));
    return r;
}
__device__ __forceinline__ float sigt(float x) {
    return fmaf(0.5f, tanha(0.5f * x), 0.5f);
}

// ---------------- scratch ----------------
__device__ float g_h[32 * MAXN];   // h_enc (post-LN), transposed [k][N]
__device__ float g_d[32 * MAXN];   // decoder init h,  transposed [k][N]

// ---------------- register-weight warp LSTM step ----------------
// Lane j owns Whh rows {j, j+32, j+64, j+96} in wreg[4*16] (f32x2 packed).
// hbuf: [32 agents][36] rows (h of agent a), cbuf same layout for c.
// xbuf: [32] float2. One __syncwarp per step handled by caller.
__device__ __forceinline__ void warp_step(
    const u64 *__restrict__ wreg, const u64 *__restrict__ wxp,
    const u64 *__restrict__ bp,
    float *hbuf, float *cbuf, const float *xbuf, int lane)
{
#pragma unroll 4
    for (int a = 0; a < 32; a++) {
        const ulonglong2 *hrow = (const ulonglong2 *)(hbuf + a * 36);
        u64 xa = *(const u64 *)(xbuf + a * 2);
        u64 a0 = fma2(wxp[0], xa, bp[0]);
        u64 a1 = fma2(wxp[1], xa, bp[1]);
        u64 a2 = fma2(wxp[2], xa, bp[2]);
        u64 a3 = fma2(wxp[3], xa, bp[3]);
#pragma unroll
        for (int kk = 0; kk < 8; kk++) {
            ulonglong2 h2 = hrow[kk];
            a0 = fma2(wreg[2 * kk],          h2.x, a0);
            a1 = fma2(wreg[16 + 2 * kk],     h2.x, a1);
            a2 = fma2(wreg[32 + 2 * kk],     h2.x, a2);
            a3 = fma2(wreg[48 + 2 * kk],     h2.x, a3);
            a0 = fma2(wreg[2 * kk + 1],      h2.y, a0);
            a1 = fma2(wreg[16 + 2 * kk + 1], h2.y, a1);
            a2 = fma2(wreg[32 + 2 * kk + 1], h2.y, a2);
            a3 = fma2(wreg[48 + 2 * kk + 1], h2.y, a3);
        }
        float gi = hsum2(a0), gf = hsum2(a1), gg = hsum2(a2), go = hsum2(a3);
        float cold = cbuf[a * 36 + lane];
        float cn = fmaf(sigt(gf), cold, sigt(gi) * tanha(gg));
        cbuf[a * 36 + lane] = cn;
        hbuf[a * 36 + lane] = sigt(go) * tanha(cn);
    }
}

// Load per-lane weights: wreg from padded shared staging, wx/bias folded thru emb.
__device__ __forceinline__ void load_weights(
    u64 *wreg, u64 *wxp, u64 *bp, const float *ws,
    const float *__restrict__ wih, const float *__restrict__ bih,
    const float *__restrict__ bhh, const float *__restrict__ embw,
    const float *__restrict__ embb, int lane)
{
#pragma unroll
    for (int g = 0; g < 4; g++) {
        const int row = g * 32 + lane;
        const ulonglong2 *r = (const ulonglong2 *)(ws + row * 36);
#pragma unroll
        for (int kk = 0; kk < 8; kk++) {
            ulonglong2 w = r[kk];
            wreg[g * 16 + 2 * kk] = w.x;
            wreg[g * 16 + 2 * kk + 1] = w.y;
        }
        float w0 = 0.f, w1 = 0.f, b = bih[row] + bhh[row];
#pragma unroll
        for (int e = 0; e < 16; e++) {
            float wie = __ldg(&wih[row * 16 + e]);
            w0 = fmaf(wie, embw[e * 2 + 0], w0);
            w1 = fmaf(wie, embw[e * 2 + 1], w1);
            b = fmaf(wie, embb[e], b);
        }
        wxp[g] = pack2(w0, w1);
        bp[g] = pack2(b, 0.f);
    }
}

// ================= K1: encoder LSTM + LayerNorm =================
__global__ void __launch_bounds__(LBT, 4)
k_enc(const float *__restrict__ rel,
      const float *__restrict__ wih, const float *__restrict__ whh_g,
      const float *__restrict__ bih, const float *__restrict__ bhh,
      const float *__restrict__ embw, const float *__restrict__ embb,
      const float *__restrict__ lng_g, const float *__restrict__ lnb_g, int n)
{
    __shared__ __align__(16) float ws[128 * 36];
    __shared__ __align__(16) float hbuf_s[2][32 * 36];
    __shared__ __align__(16) float cbuf_s[2][32 * 36];
    __shared__ __align__(16) float2 xbuf_s[2][32];
    __shared__ float lnw[64];

    const int tid = threadIdx.x, lane = tid & 31, w = tid >> 5;
    for (int i = tid; i < 4096; i += LBT)
        ws[(i >> 5) * 36 + (i & 31)] = whh_g[i];
    if (tid < 32) lnw[tid] = lng_g[tid];
    else lnw[tid] = lnb_g[tid - 32];
    __syncthreads();

    u64 wreg[64], wxp[4], bp[4];
    load_weights(wreg, wxp, bp, ws, wih, bih, bhh, embw, embb, lane);

    const int base = (blockIdx.x * 2 + w) * 32;
    if (base >= n) return;
    float *hbuf = hbuf_s[w], *cbuf = cbuf_s[w];
    float *xbuf = (float *)xbuf_s[w];

#pragma unroll
    for (int a = 0; a < 32; a++) {
        hbuf[a * 36 + lane] = 0.f;
        cbuf[a * 36 + lane] = 0.f;
    }

    const float2 *rel2 = (const float2 *)rel;
    float2 x = __ldg(&rel2[base + lane]);
#pragma unroll 1
    for (int t = 0; t < OBS_LEN; t++) {
        xbuf_s[w][lane] = x;
        if (t + 1 < OBS_LEN) x = __ldg(&rel2[(size_t)(t + 1) * n + base + lane]);
        __syncwarp();
        warp_step(wreg, wxp, bp, hbuf, cbuf, xbuf, lane);
        __syncwarp();
    }

    // LayerNorm over lane's own agent row, coalesced transposed store
    float hv[32];
    const float4 *myrow = (const float4 *)(hbuf + lane * 36);
#pragma unroll
    for (int k = 0; k < 8; k++) {
        float4 v = myrow[k];
        hv[4 * k] = v.x; hv[4 * k + 1] = v.y;
        hv[4 * k + 2] = v.z; hv[4 * k + 3] = v.w;
    }
    float m = 0.f;
#pragma unroll
    for (int j = 0; j < 32; j++) m += hv[j];
    m *= (1.f / 32.f);
    float var = 0.f;
#pragma unroll
    for (int j = 0; j < 32; j++) { float d = hv[j] - m; var = fmaf(d, d, var); }
    float inv = rsqrtf(var * (1.f / 32.f) + 1e-5f);
#pragma unroll
    for (int j = 0; j < 32; j++)
        g_h[(size_t)j * n + base + lane] = fmaf((hv[j] - m) * inv, lnw[j], lnw[32 + j]);
}

// ================= K2: attention + context LN + MLP (R3 version) =================
struct AttnSmem {
    float wq[1024], wk[1024], wv[1024], wo[1024];
    float mlp1[4096], mlp2[1536];
    float lncg[64], lncb[64], m1b[64], m2b[24], noi[8];
    float kbuf[8][32][40];
    float vbuf[8][32][40];
};

__device__ __forceinline__ float dot32p(const float *__restrict__ row, const u64 *hp)
{
    const ulonglong2 *wr = (const ulonglong2 *)row;
    u64 acc = 0ULL;
#pragma unroll
    for (int kk = 0; kk < 8; kk++) {
        ulonglong2 w = wr[kk];
        acc = fma2(w.x, hp[2 * kk], acc);
        acc = fma2(w.y, hp[2 * kk + 1], acc);
    }
    return hsum2(acc);
}
__device__ __forceinline__ float dot64p(const float *__restrict__ row, const u64 *hp)
{
    const ulonglong2 *wr = (const ulonglong2 *)row;
    u64 acc = 0ULL;
#pragma unroll
    for (int kk = 0; kk < 16; kk++) {
        ulonglong2 w = wr[kk];
        acc = fma2(w.x, hp[2 * kk], acc);
        acc = fma2(w.y, hp[2 * kk + 1], acc);
    }
    return hsum2(acc);
}

__global__ void __launch_bounds__(256)
k_attn(const float *__restrict__ wq_g, const float *__restrict__ wk_g,
       const float *__restrict__ wv_g, const float *__restrict__ wo_g,
       const float *__restrict__ lncg, const float *__restrict__ lncb,
       const float *__restrict__ m1w, const float *__restrict__ m1b,
       const float *__restrict__ m2w, const float *__restrict__ m2b,
       const float *__restrict__ noi, int n)
{
    extern __shared__ char smem_raw[];
    AttnSmem *s = (AttnSmem *)smem_raw;
    const int tid = threadIdx.x;
#define CP(d, src, c) for (int _i = tid; _i < (c); _i += 256) (d)[_i] = (src)[_i];
    CP(s->wq, wq_g, 1024) CP(s->wk, wk_g, 1024) CP(s->wv, wv_g, 1024) CP(s->wo, wo_g, 1024)
    CP(s->mlp1, m1w, 4096) CP(s->mlp2, m2w, 1536)
    CP(s->lncg, lncg, 64) CP(s->lncb, lncb, 64)
    CP(s->m1b, m1b, 64) CP(s->m2b, m2b, 24) CP(s->noi, noi, 8)
#undef CP
    __syncthreads();

    const int agent = blockIdx.x * 256 + tid;
    if (agent >= n) return;
    const int warp = tid >> 5, lane = tid & 31;

    float hv[32];
#pragma unroll
    for (int k = 0; k < 32; k++) hv[k] = __ldg(&g_h[(size_t)k * n + agent]);
    u64 hp[16];
#pragma unroll
    for (int k = 0; k < 16; k++) hp[k] = pack2(hv[2 * k], hv[2 * k + 1]);

    float q[32];
#pragma unroll
    for (int d = 0; d < 32; d++) {
        q[d] = dot32p(s->wq + d * 32, hp);
        s->kbuf[warp][lane][d] = dot32p(s->wk + d * 32, hp);
        s->vbuf[warp][lane][d] = dot32p(s->wv + d * 32, hp);
    }
    __syncwarp();

    float att[32];
#pragma unroll
    for (int hh = 0; hh < 4; hh++) {
        u64 qp[4];
#pragma unroll
        for (int i = 0; i < 4; i++) qp[i] = pack2(q[hh * 8 + 2 * i], q[hh * 8 + 2 * i + 1]);
        float sc[32], mx = -1e30f;
#pragma unroll
        for (int j = 0; j < 32; j++) {
            const ulonglong2 *kr = (const ulonglong2 *)&s->kbuf[warp][j][hh * 8];
            ulonglong2 k01 = kr[0], k23 = kr[1];
            u64 acc = fma2(k01.x, qp[0], 0ULL);
            acc = fma2(k01.y, qp[1], acc);
            acc = fma2(k23.x, qp[2], acc);
            acc = fma2(k23.y, qp[3], acc);
            float d0 = hsum2(acc) * 0.35355339059327373f;
            sc[j] = d0;
            mx = fmaxf(mx, d0);
        }
        float sum = 0.f;
#pragma unroll
        for (int j = 0; j < 32; j++) {
            float e = __expf(sc[j] - mx);
            sc[j] = e;
            sum += e;
        }
        float inv = __fdividef(1.f, sum);
        u64 a0 = 0, a1 = 0, a2 = 0, a3 = 0;
#pragma unroll
        for (int j = 0; j < 32; j++) {
            const ulonglong2 *vr = (const ulonglong2 *)&s->vbuf[warp][j][hh * 8];
            ulonglong2 v01 = vr[0], v23 = vr[1];
            u64 pd = pack2(sc[j], sc[j]);
            a0 = fma2(v01.x, pd, a0);
            a1 = fma2(v01.y, pd, a1);
            a2 = fma2(v23.x, pd, a2);
            a3 = fma2(v23.y, pd, a3);
        }
        float2 r0 = unpack2(a0), r1 = unpack2(a1), r2 = unpack2(a2), r3 = unpack2(a3);
        att[hh * 8 + 0] = r0.x * inv; att[hh * 8 + 1] = r0.y * inv;
        att[hh * 8 + 2] = r1.x * inv; att[hh * 8 + 3] = r1.y * inv;
        att[hh * 8 + 4] = r2.x * inv; att[hh * 8 + 5] = r2.y * inv;
        att[hh * 8 + 6] = r3.x * inv; att[hh * 8 + 7] = r3.y * inv;
    }

    u64 ap[16];
#pragma unroll
    for (int k = 0; k < 16; k++) ap[k] = pack2(att[2 * k], att[2 * k + 1]);
    float ctx[64];
#pragma unroll
    for (int j = 0; j < 32; j++) ctx[j] = hv[j];
#pragma unroll
    for (int d = 0; d < 32; d++) ctx[32 + d] = dot32p(s->wo + d * 32, ap);

    {
        float m = 0.f;
#pragma unroll
        for (int j = 0; j < 64; j++) m += ctx[j];
        m *= (1.f / 64.f);
        float v = 0.f;
#pragma unroll
        for (int j = 0; j < 64; j++) { float d = ctx[j] - m; v = fmaf(d, d, v); }
        float inv = rsqrtf(v * (1.f / 64.f) + 1e-5f);
#pragma unroll
        for (int j = 0; j < 64; j++)
            ctx[j] = fmaf((ctx[j] - m) * inv, s->lncg[j], s->lncb[j]);
    }

    u64 cp[32];
#pragma unroll
    for (int k = 0; k < 32; k++) cp[k] = pack2(ctx[2 * k], ctx[2 * k + 1]);
    float y1[64];
#pragma unroll
    for (int m = 0; m < 64; m++) {
        float a = dot64p(s->mlp1 + m * 64, cp) + s->m1b[m];
        y1[m] = (a > 0.f) ? a : 0.01f * a;
    }
    u64 yp[32];
#pragma unroll
    for (int k = 0; k < 32; k++) yp[k] = pack2(y1[2 * k], y1[2 * k + 1]);
#pragma unroll
    for (int m = 0; m < 24; m++) {
        float a = dot64p(s->mlp2 + m * 64, yp) + s->m2b[m];
        a = (a > 0.f) ? a : 0.01f * a;
        g_d[(size_t)m * n + agent] = a;
    }
#pragma unroll
    for (int m = 0; m < 8; m++) g_d[(size_t)(24 + m) * n + agent] = s->noi[m];
}

// ================= K3: decoder LSTM rollout =================
__global__ void __launch_bounds__(LBT, 4)
k_dec(const float *__restrict__ rel,
      const float *__restrict__ wih, const float *__restrict__ whh_g,
      const float *__restrict__ bih, const float *__restrict__ bhh,
      const float *__restrict__ embw, const float *__restrict__ embb,
      const float *__restrict__ outw_g, const float *__restrict__ outb_g,
      float *__restrict__ out, int n)
{
    __shared__ __align__(16) float ws[128 * 36];
    __shared__ __align__(16) float hbuf_s[2][32 * 36];
    __shared__ __align__(16) float cbuf_s[2][32 * 36];
    __shared__ __align__(16) float2 xbuf_s[2][32];
    __shared__ __align__(16) float outw_s[64];
    __shared__ float outb_s[2];

    const int tid = threadIdx.x, lane = tid & 31, w = tid >> 5;
    for (int i = tid; i < 4096; i += LBT)
        ws[(i >> 5) * 36 + (i & 31)] = whh_g[i];
    if (tid < 64) outw_s[tid] = outw_g[tid];
    if (tid < 2) outb_s[tid] = outb_g[tid];
    __syncthreads();

    u64 wreg[64], wxp[4], bp[4];
    load_weights(wreg, wxp, bp, ws, wih, bih, bhh, embw, embb, lane);

    const int base = (blockIdx.x * 2 + w) * 32;
    if (base >= n) return;
    float *hbuf = hbuf_s[w], *cbuf = cbuf_s[w];
    float *xbuf = (float *)xbuf_s[w];

    // init: lane owns agent `lane`'s h row; c = 0
#pragma unroll
    for (int k = 0; k < 32; k++)
        hbuf[lane * 36 + k] = g_d[(size_t)k * n + base + lane];
#pragma unroll
    for (int a = 0; a < 32; a++) cbuf[a * 36 + lane] = 0.f;

    const float2 *rel2 = (const float2 *)rel;
    float2 *out2 = (float2 *)out;
    xbuf_s[w][lane] = __ldg(&rel2[(size_t)(OBS_LEN - 1) * n + base + lane]);
    __syncwarp();

#pragma unroll 1
    for (int t = 0; t < PRED_LEN; t++) {
        warp_step(wreg, wxp, bp, hbuf, cbuf, xbuf, lane);
        __syncwarp();
        // output projection on lane's own agent row
        const float4 *myrow = (const float4 *)(hbuf + lane * 36);
        const ulonglong2 *w0 = (const ulonglong2 *)outw_s;
        const ulonglong2 *w1 = (const ulonglong2 *)(outw_s + 32);
        u64 ax = 0ULL, ay = 0ULL;
#pragma unroll
        for (int kk = 0; kk < 8; kk++) {
            float4 h4 = myrow[kk];
            u64 h01 = pack2(h4.x, h4.y);
            u64 h23 = pack2(h4.z, h4.w);
            ulonglong2 wx4 = w0[kk];
            ulonglong2 wy4 = w1[kk];
            ax = fma2(wx4.x, h01, ax);
            ax = fma2(wx4.y, h23, ax);
            ay = fma2(wy4.x, h01, ay);
            ay = fma2(wy4.y, h23, ay);
        }
        float ox = hsum2(ax) + outb_s[0];
        float oy = hsum2(ay) + outb_s[1];
        out2[(size_t)t * n + base + lane] = make_float2(ox, oy);
        xbuf_s[w][lane] = make_float2(ox, oy);
        __syncwarp();
    }
}

// ================= launch =================
extern "C" void kernel_launch(void *const *d_in, const int *in_sizes, int n_in,
                              void *d_out, int out_size)
{
    const float *rel = (const float *)d_in[1];
    const float *noise = (const float *)d_in[3];
    const float *enc_emb_w = (const float *)d_in[4];
    const float *enc_emb_b = (const float *)d_in[5];
    const float *enc_wih = (const float *)d_in[6];
    const float *enc_whh = (const float *)d_in[7];
    const float *enc_bih = (const float *)d_in[8];
    const float *enc_bhh = (const float *)d_in[9];
    const float *lne_g = (const float *)d_in[10];
    const float *lne_b = (const float *)d_in[11];
    const float *wq = (const float *)d_in[12];
    const float *wk = (const float *)d_in[13];
    const float *wv = (const float *)d_in[14];
    const float *wo = (const float *)d_in[15];
    const float *lnc_g = (const float *)d_in[16];
    const float *lnc_b = (const float *)d_in[17];
    const float *mlp1_w = (const float *)d_in[18];
    const float *mlp1_b = (const float *)d_in[19];
    const float *mlp2_w = (const float *)d_in[20];
    const float *mlp2_b = (const float *)d_in[21];
    const float *dec_emb_w = (const float *)d_in[22];
    const float *dec_emb_b = (const float *)d_in[23];
    const float *dec_wih = (const float *)d_in[24];
    const float *dec_whh = (const float *)d_in[25];
    const float *dec_bih = (const float *)d_in[26];
    const float *dec_bhh = (const float *)d_in[27];
    const float *dec_out_w = (const float *)d_in[28];
    const float *dec_out_b = (const float *)d_in[29];

    int n = in_sizes[1] / (OBS_LEN * 2);

    static bool attr_set = false;
    if (!attr_set) {
        cudaFuncSetAttribute(k_attn, cudaFuncAttributeMaxDynamicSharedMemorySize,
                             (int)sizeof(AttnSmem));
        attr_set = true;
    }

    int gridp = (n + LBT - 1) / LBT;   // 2 warps/CTA, 32 agents/warp

    k_enc<<<gridp, LBT>>>(rel, enc_wih, enc_whh, enc_bih, enc_bhh,
                          enc_emb_w, enc_emb_b, lne_g, lne_b, n);
    k_attn<<<(n + 255) / 256, 256, sizeof(AttnSmem)>>>(
        wq, wk, wv, wo, lnc_g, lnc_b,
        mlp1_w, mlp1_b, mlp2_w, mlp2_b, noise, n);
    k_dec<<<gridp, LBT>>>(rel, dec_wih, dec_whh, dec_bih, dec_bhh,
                          dec_emb_w, dec_emb_b, dec_out_w, dec_out_b,
                          (float *)d_out, n);
}

// round 6
// speedup vs baseline: 1.0925x; 1.0012x over previous
#include <cuda_runtime.h>

#define OBS_LEN 20
#define PRED_LEN 30
#define MAXN 131072
#define LBT 64           // LSTM kernels: 64 threads = 2 warps/CTA

typedef unsigned long long u64;

// ---------------- f32x2 / MUFU helpers ----------------
__device__ __forceinline__ u64 fma2(u64 a, u64 b, u64 c) {
    u64 d;
    asm("fma.rn.f32x2 %0, %1, %2, %3;" : "=l"(d) : "l"(a), "l"(b), "l"(c));
    return d;
}
__device__ __forceinline__ u64 pack2(float lo, float hi) {
    u64 d;
    asm("mov.b64 %0, {%1, %2};" : "=l"(d) : "f"(lo), "f"(hi));
    return d;
}
__device__ __forceinline__ float2 unpack2(u64 v) {
    float2 r;
    asm("mov.b64 {%0, %1}, %2;" : "=f"(r.x), "=f"(r.y) : "l"(v));
    return r;
}
__device__ __forceinline__ float hsum2(u64 v) {
    float2 s = unpack2(v);
    return s.x + s.y;
}
__device__ __forceinline__ float tanha(float x) {
    float r;
    asm("tanh.approx.f32 %0, %1;" : "=f"(r) : "f"(x));
    return r;
}
__device__ __forceinline__ float sigt(float x) {
    return fmaf(0.5f, tanha(0.5f * x), 0.5f);
}

// ---------------- scratch ----------------
__device__ float g_h[32 * MAXN];   // h_enc (post-LN), transposed [k][N]
__device__ float g_d[32 * MAXN];   // decoder init h,  transposed [k][N]

// ---------------- register-weight warp LSTM step ----------------
// Lane j owns Whh rows {j, j+32, j+64, j+96} in wreg[64] (f32x2 packed).
// wxb[r] = { pack(wx0,wx1), pack(bias,0) } in SMEM (broadcast reads).
// hbuf: [32 agents][36]; cbuf same; xbuf [32] float2.
__device__ __forceinline__ void warp_step(
    const u64 *__restrict__ wreg, const ulonglong2 *__restrict__ wxb,
    float *hbuf, float *cbuf, const float *xbuf, int lane)
{
#pragma unroll 4
    for (int a = 0; a < 32; a++) {
        const ulonglong2 *hrow = (const ulonglong2 *)(hbuf + a * 36);
        u64 xa = *(const u64 *)(xbuf + a * 2);
        ulonglong2 wx0 = wxb[lane];
        ulonglong2 wx1 = wxb[32 + lane];
        ulonglong2 wx2 = wxb[64 + lane];
        ulonglong2 wx3 = wxb[96 + lane];
        u64 a0 = fma2(wx0.x, xa, wx0.y);
        u64 a1 = fma2(wx1.x, xa, wx1.y);
        u64 a2 = fma2(wx2.x, xa, wx2.y);
        u64 a3 = fma2(wx3.x, xa, wx3.y);
#pragma unroll
        for (int kk = 0; kk < 8; kk++) {
            ulonglong2 h2 = hrow[kk];
            a0 = fma2(wreg[2 * kk],          h2.x, a0);
            a1 = fma2(wreg[16 + 2 * kk],     h2.x, a1);
            a2 = fma2(wreg[32 + 2 * kk],     h2.x, a2);
            a3 = fma2(wreg[48 + 2 * kk],     h2.x, a3);
            a0 = fma2(wreg[2 * kk + 1],      h2.y, a0);
            a1 = fma2(wreg[16 + 2 * kk + 1], h2.y, a1);
            a2 = fma2(wreg[32 + 2 * kk + 1], h2.y, a2);
            a3 = fma2(wreg[48 + 2 * kk + 1], h2.y, a3);
        }
        float gi = hsum2(a0), gf = hsum2(a1), gg = hsum2(a2), go = hsum2(a3);
        float cold = cbuf[a * 36 + lane];
        float cn = fmaf(sigt(gf), cold, sigt(gi) * tanha(gg));
        cbuf[a * 36 + lane] = cn;
        hbuf[a * 36 + lane] = sigt(go) * tanha(cn);
    }
}

// Load lane's Whh rows straight from global (one-time; L2-cached).
__device__ __forceinline__ void load_wreg(
    u64 *wreg, const float *__restrict__ whh_g, int lane)
{
#pragma unroll
    for (int g = 0; g < 4; g++) {
        const int row = g * 32 + lane;
        const float4 *r = (const float4 *)(whh_g + row * 32);
#pragma unroll
        for (int kk = 0; kk < 8; kk++) {
            float4 w = __ldg(&r[kk]);
            wreg[g * 16 + 2 * kk]     = pack2(w.x, w.y);
            wreg[g * 16 + 2 * kk + 1] = pack2(w.z, w.w);
        }
    }
}

// Fold input weights + biases through the embedding into SMEM wxb.
__device__ __forceinline__ void fold_wxb(
    ulonglong2 *wxb, int row,
    const float *__restrict__ wih, const float *__restrict__ bih,
    const float *__restrict__ bhh, const float *__restrict__ embw,
    const float *__restrict__ embb)
{
    float w0 = 0.f, w1 = 0.f, b = bih[row] + bhh[row];
#pragma unroll
    for (int e = 0; e < 16; e++) {
        float wie = __ldg(&wih[row * 16 + e]);
        w0 = fmaf(wie, embw[e * 2 + 0], w0);
        w1 = fmaf(wie, embw[e * 2 + 1], w1);
        b = fmaf(wie, embb[e], b);
    }
    wxb[row].x = pack2(w0, w1);
    wxb[row].y = pack2(b, 0.f);
}

// ================= K1: encoder LSTM + LayerNorm =================
__global__ void __launch_bounds__(LBT, 6)
k_enc(const float *__restrict__ rel,
      const float *__restrict__ wih, const float *__restrict__ whh_g,
      const float *__restrict__ bih, const float *__restrict__ bhh,
      const float *__restrict__ embw, const float *__restrict__ embb,
      const float *__restrict__ lng_g, const float *__restrict__ lnb_g, int n)
{
    __shared__ __align__(16) ulonglong2 wxb[128];
    __shared__ __align__(16) float hbuf_s[2][32 * 36];
    __shared__ __align__(16) float cbuf_s[2][32 * 36];
    __shared__ __align__(16) float2 xbuf_s[2][32];
    __shared__ float lnw[64];

    const int tid = threadIdx.x, lane = tid & 31, w = tid >> 5;
    for (int g = tid; g < 128; g += LBT)
        fold_wxb(wxb, g, wih, bih, bhh, embw, embb);
    if (tid < 32) lnw[tid] = lng_g[tid];
    else lnw[tid] = lnb_g[tid - 32];

    u64 wreg[64];
    load_wreg(wreg, whh_g, lane);
    __syncthreads();

    const int base = (blockIdx.x * 2 + w) * 32;
    if (base >= n) return;
    float *hbuf = hbuf_s[w], *cbuf = cbuf_s[w];
    float *xbuf = (float *)xbuf_s[w];

#pragma unroll
    for (int a = 0; a < 32; a++) {
        hbuf[a * 36 + lane] = 0.f;
        cbuf[a * 36 + lane] = 0.f;
    }

    const float2 *rel2 = (const float2 *)rel;
    float2 x = __ldg(&rel2[base + lane]);
#pragma unroll 1
    for (int t = 0; t < OBS_LEN; t++) {
        xbuf_s[w][lane] = x;
        if (t + 1 < OBS_LEN) x = __ldg(&rel2[(size_t)(t + 1) * n + base + lane]);
        __syncwarp();
        warp_step(wreg, wxb, hbuf, cbuf, xbuf, lane);
        __syncwarp();
    }

    // LayerNorm over lane's own agent row, coalesced transposed store
    float hv[32];
    const float4 *myrow = (const float4 *)(hbuf + lane * 36);
#pragma unroll
    for (int k = 0; k < 8; k++) {
        float4 v = myrow[k];
        hv[4 * k] = v.x; hv[4 * k + 1] = v.y;
        hv[4 * k + 2] = v.z; hv[4 * k + 3] = v.w;
    }
    float m = 0.f;
#pragma unroll
    for (int j = 0; j < 32; j++) m += hv[j];
    m *= (1.f / 32.f);
    float var = 0.f;
#pragma unroll
    for (int j = 0; j < 32; j++) { float d = hv[j] - m; var = fmaf(d, d, var); }
    float inv = rsqrtf(var * (1.f / 32.f) + 1e-5f);
#pragma unroll
    for (int j = 0; j < 32; j++)
        g_h[(size_t)j * n + base + lane] = fmaf((hv[j] - m) * inv, lnw[j], lnw[32 + j]);
}

// ================= K2: attention + context LN + MLP =================
struct AttnSmem {
    float wq[1024], wk[1024], wv[1024], wo[1024];
    float mlp1[4096], mlp2[1536];
    float lncg[64], lncb[64], m1b[64], m2b[24], noi[8];
    float kbuf[8][32][40];
    float vbuf[8][32][40];
};

__device__ __forceinline__ float dot32p(const float *__restrict__ row, const u64 *hp)
{
    const ulonglong2 *wr = (const ulonglong2 *)row;
    u64 acc = 0ULL;
#pragma unroll
    for (int kk = 0; kk < 8; kk++) {
        ulonglong2 w = wr[kk];
        acc = fma2(w.x, hp[2 * kk], acc);
        acc = fma2(w.y, hp[2 * kk + 1], acc);
    }
    return hsum2(acc);
}
__device__ __forceinline__ float dot64p(const float *__restrict__ row, const u64 *hp)
{
    const ulonglong2 *wr = (const ulonglong2 *)row;
    u64 acc = 0ULL;
#pragma unroll
    for (int kk = 0; kk < 16; kk++) {
        ulonglong2 w = wr[kk];
        acc = fma2(w.x, hp[2 * kk], acc);
        acc = fma2(w.y, hp[2 * kk + 1], acc);
    }
    return hsum2(acc);
}

__global__ void __launch_bounds__(256)
k_attn(const float *__restrict__ wq_g, const float *__restrict__ wk_g,
       const float *__restrict__ wv_g, const float *__restrict__ wo_g,
       const float *__restrict__ lncg, const float *__restrict__ lncb,
       const float *__restrict__ m1w, const float *__restrict__ m1b,
       const float *__restrict__ m2w, const float *__restrict__ m2b,
       const float *__restrict__ noi, int n)
{
    extern __shared__ char smem_raw[];
    AttnSmem *s = (AttnSmem *)smem_raw;
    const int tid = threadIdx.x;
#define CP(d, src, c) for (int _i = tid; _i < (c); _i += 256) (d)[_i] = (src)[_i];
    CP(s->wq, wq_g, 1024) CP(s->wk, wk_g, 1024) CP(s->wv, wv_g, 1024) CP(s->wo, wo_g, 1024)
    CP(s->mlp1, m1w, 4096) CP(s->mlp2, m2w, 1536)
    CP(s->lncg, lncg, 64) CP(s->lncb, lncb, 64)
    CP(s->m1b, m1b, 64) CP(s->m2b, m2b, 24) CP(s->noi, noi, 8)
#undef CP
    __syncthreads();

    const int agent = blockIdx.x * 256 + tid;
    if (agent >= n) return;
    const int warp = tid >> 5, lane = tid & 31;

    float hv[32];
#pragma unroll
    for (int k = 0; k < 32; k++) hv[k] = __ldg(&g_h[(size_t)k * n + agent]);
    u64 hp[16];
#pragma unroll
    for (int k = 0; k < 16; k++) hp[k] = pack2(hv[2 * k], hv[2 * k + 1]);

    float q[32];
#pragma unroll
    for (int d = 0; d < 32; d++) {
        q[d] = dot32p(s->wq + d * 32, hp);
        s->kbuf[warp][lane][d] = dot32p(s->wk + d * 32, hp);
        s->vbuf[warp][lane][d] = dot32p(s->wv + d * 32, hp);
    }
    __syncwarp();

    float att[32];
#pragma unroll
    for (int hh = 0; hh < 4; hh++) {
        u64 qp[4];
#pragma unroll
        for (int i = 0; i < 4; i++) qp[i] = pack2(q[hh * 8 + 2 * i], q[hh * 8 + 2 * i + 1]);
        float sc[32], mx = -1e30f;
#pragma unroll
        for (int j = 0; j < 32; j++) {
            const ulonglong2 *kr = (const ulonglong2 *)&s->kbuf[warp][j][hh * 8];
            ulonglong2 k01 = kr[0], k23 = kr[1];
            u64 acc = fma2(k01.x, qp[0], 0ULL);
            acc = fma2(k01.y, qp[1], acc);
            acc = fma2(k23.x, qp[2], acc);
            acc = fma2(k23.y, qp[3], acc);
            float d0 = hsum2(acc) * 0.35355339059327373f;
            sc[j] = d0;
            mx = fmaxf(mx, d0);
        }
        float sum = 0.f;
#pragma unroll
        for (int j = 0; j < 32; j++) {
            float e = __expf(sc[j] - mx);
            sc[j] = e;
            sum += e;
        }
        float inv = __fdividef(1.f, sum);
        u64 a0 = 0, a1 = 0, a2 = 0, a3 = 0;
#pragma unroll
        for (int j = 0; j < 32; j++) {
            const ulonglong2 *vr = (const ulonglong2 *)&s->vbuf[warp][j][hh * 8];
            ulonglong2 v01 = vr[0], v23 = vr[1];
            u64 pd = pack2(sc[j], sc[j]);
            a0 = fma2(v01.x, pd, a0);
            a1 = fma2(v01.y, pd, a1);
            a2 = fma2(v23.x, pd, a2);
            a3 = fma2(v23.y, pd, a3);
        }
        float2 r0 = unpack2(a0), r1 = unpack2(a1), r2 = unpack2(a2), r3 = unpack2(a3);
        att[hh * 8 + 0] = r0.x * inv; att[hh * 8 + 1] = r0.y * inv;
        att[hh * 8 + 2] = r1.x * inv; att[hh * 8 + 3] = r1.y * inv;
        att[hh * 8 + 4] = r2.x * inv; att[hh * 8 + 5] = r2.y * inv;
        att[hh * 8 + 6] = r3.x * inv; att[hh * 8 + 7] = r3.y * inv;
    }

    u64 ap[16];
#pragma unroll
    for (int k = 0; k < 16; k++) ap[k] = pack2(att[2 * k], att[2 * k + 1]);
    float ctx[64];
#pragma unroll
    for (int j = 0; j < 32; j++) ctx[j] = hv[j];
#pragma unroll
    for (int d = 0; d < 32; d++) ctx[32 + d] = dot32p(s->wo + d * 32, ap);

    {
        float m = 0.f;
#pragma unroll
        for (int j = 0; j < 64; j++) m += ctx[j];
        m *= (1.f / 64.f);
        float v = 0.f;
#pragma unroll
        for (int j = 0; j < 64; j++) { float d = ctx[j] - m; v = fmaf(d, d, v); }
        float inv = rsqrtf(v * (1.f / 64.f) + 1e-5f);
#pragma unroll
        for (int j = 0; j < 64; j++)
            ctx[j] = fmaf((ctx[j] - m) * inv, s->lncg[j], s->lncb[j]);
    }

    u64 cp[32];
#pragma unroll
    for (int k = 0; k < 32; k++) cp[k] = pack2(ctx[2 * k], ctx[2 * k + 1]);
    float y1[64];
#pragma unroll
    for (int m = 0; m < 64; m++) {
        float a = dot64p(s->mlp1 + m * 64, cp) + s->m1b[m];
        y1[m] = (a > 0.f) ? a : 0.01f * a;
    }
    u64 yp[32];
#pragma unroll
    for (int k = 0; k < 32; k++) yp[k] = pack2(y1[2 * k], y1[2 * k + 1]);
#pragma unroll
    for (int m = 0; m < 24; m++) {
        float a = dot64p(s->mlp2 + m * 64, yp) + s->m2b[m];
        a = (a > 0.f) ? a : 0.01f * a;
        g_d[(size_t)m * n + agent] = a;
    }
#pragma unroll
    for (int m = 0; m < 8; m++) g_d[(size_t)(24 + m) * n + agent] = s->noi[m];
}

// ================= K3: decoder LSTM rollout =================
__global__ void __launch_bounds__(LBT, 6)
k_dec(const float *__restrict__ rel,
      const float *__restrict__ wih, const float *__restrict__ whh_g,
      const float *__restrict__ bih, const float *__restrict__ bhh,
      const float *__restrict__ embw, const float *__restrict__ embb,
      const float *__restrict__ outw_g, const float *__restrict__ outb_g,
      float *__restrict__ out, int n)
{
    __shared__ __align__(16) ulonglong2 wxb[128];
    __shared__ __align__(16) float hbuf_s[2][32 * 36];
    __shared__ __align__(16) float cbuf_s[2][32 * 36];
    __shared__ __align__(16) float2 xbuf_s[2][32];
    __shared__ __align__(16) float outw_s[64];
    __shared__ float outb_s[2];

    const int tid = threadIdx.x, lane = tid & 31, w = tid >> 5;
    for (int g = tid; g < 128; g += LBT)
        fold_wxb(wxb, g, wih, bih, bhh, embw, embb);
    if (tid < 64) outw_s[tid] = outw_g[tid];
    if (tid < 2) outb_s[tid] = outb_g[tid];

    u64 wreg[64];
    load_wreg(wreg, whh_g, lane);
    __syncthreads();

    const int base = (blockIdx.x * 2 + w) * 32;
    if (base >= n) return;
    float *hbuf = hbuf_s[w], *cbuf = cbuf_s[w];
    float *xbuf = (float *)xbuf_s[w];

    // init: lane owns agent `lane`'s h row; c = 0
#pragma unroll
    for (int k = 0; k < 32; k++)
        hbuf[lane * 36 + k] = g_d[(size_t)k * n + base + lane];
#pragma unroll
    for (int a = 0; a < 32; a++) cbuf[a * 36 + lane] = 0.f;

    const float2 *rel2 = (const float2 *)rel;
    float2 *out2 = (float2 *)out;
    xbuf_s[w][lane] = __ldg(&rel2[(size_t)(OBS_LEN - 1) * n + base + lane]);
    __syncwarp();

#pragma unroll 1
    for (int t = 0; t < PRED_LEN; t++) {
        warp_step(wreg, wxb, hbuf, cbuf, xbuf, lane);
        __syncwarp();
        // output projection on lane's own agent row
        const float4 *myrow = (const float4 *)(hbuf + lane * 36);
        const ulonglong2 *w0 = (const ulonglong2 *)outw_s;
        const ulonglong2 *w1 = (const ulonglong2 *)(outw_s + 32);
        u64 ax = 0ULL, ay = 0ULL;
#pragma unroll
        for (int kk = 0; kk < 8; kk++) {
            float4 h4 = myrow[kk];
            u64 h01 = pack2(h4.x, h4.y);
            u64 h23 = pack2(h4.z, h4.w);
            ulonglong2 wx4 = w0[kk];
            ulonglong2 wy4 = w1[kk];
            ax = fma2(wx4.x, h01, ax);
            ax = fma2(wx4.y, h23, ax);
            ay = fma2(wy4.x, h01, ay);
            ay = fma2(wy4.y, h23, ay);
        }
        float ox = hsum2(ax) + outb_s[0];
        float oy = hsum2(ay) + outb_s[1];
        out2[(size_t)t * n + base + lane] = make_float2(ox, oy);
        xbuf_s[w][lane] = make_float2(ox, oy);
        __syncwarp();
    }
}

// ================= launch =================
extern "C" void kernel_launch(void *const *d_in, const int *in_sizes, int n_in,
                              void *d_out, int out_size)
{
    const float *rel = (const float *)d_in[1];
    const float *noise = (const float *)d_in[3];
    const float *enc_emb_w = (const float *)d_in[4];
    const float *enc_emb_b = (const float *)d_in[5];
    const float *enc_wih = (const float *)d_in[6];
    const float *enc_whh = (const float *)d_in[7];
    const float *enc_bih = (const float *)d_in[8];
    const float *enc_bhh = (const float *)d_in[9];
    const float *lne_g = (const float *)d_in[10];
    const float *lne_b = (const float *)d_in[11];
    const float *wq = (const float *)d_in[12];
    const float *wk = (const float *)d_in[13];
    const float *wv = (const float *)d_in[14];
    const float *wo = (const float *)d_in[15];
    const float *lnc_g = (const float *)d_in[16];
    const float *lnc_b = (const float *)d_in[17];
    const float *mlp1_w = (const float *)d_in[18];
    const float *mlp1_b = (const float *)d_in[19];
    const float *mlp2_w = (const float *)d_in[20];
    const float *mlp2_b = (const float *)d_in[21];
    const float *dec_emb_w = (const float *)d_in[22];
    const float *dec_emb_b = (const float *)d_in[23];
    const float *dec_wih = (const float *)d_in[24];
    const float *dec_whh = (const float *)d_in[25];
    const float *dec_bih = (const float *)d_in[26];
    const float *dec_bhh = (const float *)d_in[27];
    const float *dec_out_w = (const float *)d_in[28];
    const float *dec_out_b = (const float *)d_in[29];

    int n = in_sizes[1] / (OBS_LEN * 2);

    static bool attr_set = false;
    if (!attr_set) {
        cudaFuncSetAttribute(k_attn, cudaFuncAttributeMaxDynamicSharedMemorySize,
                             (int)sizeof(AttnSmem));
        attr_set = true;
    }

    int gridp = (n + LBT - 1) / LBT;   // 2 warps/CTA, 32 agents/warp

    k_enc<<<gridp, LBT>>>(rel, enc_wih, enc_whh, enc_bih, enc_bhh,
                          enc_emb_w, enc_emb_b, lne_g, lne_b, n);
    k_attn<<<(n + 255) / 256, 256, sizeof(AttnSmem)>>>(
        wq, wk, wv, wo, lnc_g, lnc_b,
        mlp1_w, mlp1_b, mlp2_w, mlp2_b, noise, n);
    k_dec<<<gridp, LBT>>>(rel, dec_wih, dec_whh, dec_bih, dec_bhh,
                          dec_emb_w, dec_emb_b, dec_out_w, dec_out_b,
                          (float *)d_out, n);
}